// round 10
// baseline (speedup 1.0000x reference)
#include <cuda_runtime.h>
#include <cuda_bf16.h>
#include <cstdint>
#include <math.h>

// ---------------------------------------------------------------------------
// Problem constants
// ---------------------------------------------------------------------------
#define TT   2048
#define EDIM 256
#define H2D  256
#define LDIM 32
#define RTOT 2048   // 2 dirs * 4 gates * 256
#define NCHUNK 128
#define CLEN   16   // CRF steps per chunk

// ---------------------------------------------------------------------------
// Scratch
// ---------------------------------------------------------------------------
__device__ float g_zin[TT * RTOT];        // 16 MB (L2-resident)
__device__ float g_hs[TT * 512];          // 4 MB
__device__ float g_logits[TT * LDIM];     // 256 KB
__device__ float g_P[NCHUNK * 1024];      // 512 KB
__device__ float g_lsc[NCHUNK];

// ---------------------------------------------------------------------------
// Helpers
// ---------------------------------------------------------------------------
__device__ __forceinline__ uint32_t s2u(const void* p) {
    uint32_t a;
    asm("{ .reg .u64 t; cvta.to.shared.u64 t, %1; cvt.u32.u64 %0, t; }"
        : "=r"(a) : "l"(p));
    return a;
}
__device__ __forceinline__ void cluster_sync_() {
    asm volatile("barrier.cluster.arrive.aligned;\n\t"
                 "barrier.cluster.wait.aligned;" ::: "memory");
}
__device__ __forceinline__ uint32_t my_ctarank() {
    uint32_t r;
    asm("mov.u32 %0, %%cluster_ctarank;" : "=r"(r));
    return r;
}
__device__ __forceinline__ uint32_t mapa_(uint32_t a, uint32_t r) {
    uint32_t d;
    asm("mapa.shared::cluster.u32 %0, %1, %2;" : "=r"(d) : "r"(a), "r"(r));
    return d;
}
__device__ __forceinline__ unsigned long long ffma2(unsigned long long a,
                                                    unsigned long long b,
                                                    unsigned long long c) {
    unsigned long long d;
    asm("fma.rn.f32x2 %0, %1, %2, %3;" : "=l"(d) : "l"(a), "l"(b), "l"(c));
    return d;
}
__device__ __forceinline__ float lo32(unsigned long long v) { return __uint_as_float((unsigned)v); }
__device__ __forceinline__ float hi32(unsigned long long v) { return __uint_as_float((unsigned)(v >> 32)); }

// 64-byte cluster bulk copy: local smem -> peer smem, complete_tx at peer mbar.
__device__ __forceinline__ void bulk_copy64(uint32_t dst, uint32_t src, uint32_t dmbar) {
    asm volatile(
        "cp.async.bulk.shared::cluster.shared::cta.mbarrier::complete_tx::bytes [%0], [%1], %2, [%3];"
        :: "r"(dst), "r"(src), "r"(64u), "r"(dmbar) : "memory");
}
__device__ __forceinline__ void fence_proxy_async_() {
    asm volatile("fence.proxy.async.shared::cta;" ::: "memory");
}

#define MBAR_INIT(a, n) \
    asm volatile("mbarrier.init.shared.b64 [%0], %1;" :: "r"(a), "r"((uint32_t)(n)) : "memory")
#define MBAR_EXPECT_TX(a, n) \
    asm volatile("mbarrier.arrive.expect_tx.shared.b64 _, [%0], %1;" :: "r"(a), "r"((uint32_t)(n)) : "memory")

__device__ __forceinline__ void mbar_wait_parity(uint32_t mbar, uint32_t parity) {
    uint32_t done;
    asm volatile(
        "{\n\t.reg .pred p;\n\t"
        "mbarrier.try_wait.parity.acquire.cta.shared::cta.b64 p, [%1], %2;\n\t"
        "selp.b32 %0, 1, 0, p;\n\t}"
        : "=r"(done) : "r"(mbar), "r"(parity) : "memory");
    if (!done) {
        asm volatile(
            "{\n\t.reg .pred P1;\n\t"
            "WL_%=:\n\t"
            "mbarrier.try_wait.parity.acquire.cta.shared::cta.b64 P1, [%0], %1, 0x989680;\n\t"
            "@P1 bra.uni WD_%=;\n\t"
            "bra.uni WL_%=;\n\t"
            "WD_%=:\n\t}"
            :: "r"(mbar), "r"(parity) : "memory");
    }
}

// Fast activations (rel_err 0.0 proven over 2048 steps)
__device__ __forceinline__ float tanh_ap(float x) {
    float y;
    asm("tanh.approx.f32 %0, %1;" : "=f"(y) : "f"(x));
    return y;
}
__device__ __forceinline__ float fsigm(float x) {
    return __fmaf_rn(0.5f, tanh_ap(0.5f * x), 0.5f);
}

// ---------------------------------------------------------------------------
// Dummy kernel: shifts lstm_kernel to captured launch index 3.
// ---------------------------------------------------------------------------
__global__ void dummy_kernel() {}

// ---------------------------------------------------------------------------
// Kernel 1: Zin[t][col] = emb[ids[t]] @ Wih^T + b
// ---------------------------------------------------------------------------
__global__ __launch_bounds__(256) void zin_kernel(
    const int* __restrict__ ids, const float* __restrict__ emb,
    const float* __restrict__ wihf, const float* __restrict__ wihb,
    const float* __restrict__ bf, const float* __restrict__ bb)
{
    __shared__ float As[32][68];
    __shared__ float Bs[32][68];
    __shared__ int gids[64];

    const int tid = threadIdx.x;
    const int tx = tid & 15;
    const int ty = tid >> 4;
    const int tRow = blockIdx.y * 64;
    const int nCol = blockIdx.x * 64;

    if (tid < 64) gids[tid] = ids[tRow + tid];
    __syncthreads();

    float acc[4][4];
#pragma unroll
    for (int i = 0; i < 4; i++)
#pragma unroll
        for (int j = 0; j < 4; j++) acc[i][j] = 0.f;

    for (int kk = 0; kk < EDIM; kk += 32) {
#pragma unroll
        for (int u = 0; u < 2; u++) {
            int idx = tid + u * 256;
            int row = idx >> 3;
            int c4  = (idx & 7) * 4;
            const float4 av = *(const float4*)(emb + (size_t)gids[row] * EDIM + kk + c4);
            As[c4 + 0][row] = av.x; As[c4 + 1][row] = av.y;
            As[c4 + 2][row] = av.z; As[c4 + 3][row] = av.w;
            int brow = nCol + row;
            const float* bp = (brow < 1024)
                ? (wihf + (size_t)brow * EDIM)
                : (wihb + (size_t)(brow - 1024) * EDIM);
            const float4 bv = *(const float4*)(bp + kk + c4);
            Bs[c4 + 0][row] = bv.x; Bs[c4 + 1][row] = bv.y;
            Bs[c4 + 2][row] = bv.z; Bs[c4 + 3][row] = bv.w;
        }
        __syncthreads();
#pragma unroll
        for (int k = 0; k < 32; k++) {
            const float4 av = *(const float4*)&As[k][ty * 4];
            const float4 bv = *(const float4*)&Bs[k][tx * 4];
            const float ar[4] = {av.x, av.y, av.z, av.w};
            const float br[4] = {bv.x, bv.y, bv.z, bv.w};
#pragma unroll
            for (int i = 0; i < 4; i++)
#pragma unroll
                for (int j = 0; j < 4; j++) acc[i][j] += ar[i] * br[j];
        }
        __syncthreads();
    }

    const int colBase = nCol + tx * 4;
    float bias[4];
#pragma unroll
    for (int j = 0; j < 4; j++) {
        int c = colBase + j;
        bias[j] = (c < 1024) ? bf[c] : bb[c - 1024];
    }
#pragma unroll
    for (int i = 0; i < 4; i++) {
        int row = tRow + ty * 4 + i;
        float4 o;
        o.x = acc[i][0] + bias[0];
        o.y = acc[i][1] + bias[1];
        o.z = acc[i][2] + bias[2];
        o.w = acc[i][3] + bias[3];
        *(float4*)(g_zin + (size_t)row * RTOT + colBase) = o;
    }
}

// ---------------------------------------------------------------------------
// Kernel 2: BiLSTM recurrence. 2 clusters of 16 CTAs (fwd / bwd).
// h exchange: 16 writer lanes stage 64 B locally; each lane issues ONE 64-B
// cp.async.bulk to rank=lane. Arrivals per dest mbar: 16/step (was 256).
// ---------------------------------------------------------------------------
__global__ void __launch_bounds__(256, 1) __cluster_dims__(16, 1, 1)
lstm_kernel(const float* __restrict__ whhf, const float* __restrict__ whhb,
            const float* __restrict__ h0, const float* __restrict__ c0)
{
    __shared__ __align__(128) float h_s[2][256];
    __shared__ __align__(16) float z_s[64][4];      // [gate row][column quarter]
    __shared__ __align__(64) float h_stage[2][16];  // staged own-slice (64 B)
    __shared__ unsigned long long mbar[2];

    const int tid  = threadIdx.x;
    const int dir  = blockIdx.x >> 4;
    const uint32_t rank = my_ctarank();

    const int q    = tid & 3;        // column quarter
    const int lr   = tid >> 2;       // local gate row 0..63
    const int gate = lr >> 4;
    const int jr   = lr & 15;
    const int grow = gate * 256 + (int)rank * 16 + jr;

    const float* whh = dir ? whhb : whhf;

    unsigned long long w2[32];
    {
        const float* wr = whh + (size_t)grow * H2D + q * 64;
#pragma unroll
        for (int k = 0; k < 16; k++) {
            int m = (k + 2 * q) & 15;
            const unsigned long long* p = (const unsigned long long*)(wr + m * 4);
            w2[2 * k]     = p[0];
            w2[2 * k + 1] = p[1];
        }
    }

    // Writers: warp 0 lanes 0..15, one unique h index each (jj = tid).
    const bool writer = (tid < 16);
    const int  jj     = tid;                       // valid when writer

    float c_reg = 0.f;
    if (writer) c_reg = c0[dir * H2D + (int)rank * 16 + jj];

    h_s[0][tid] = h0[dir * H2D + tid];

    // Each writer lane targets rank = lane: our 64-B slice in that rank's h_s.
    uint32_t dst_h[2], dst_m[2];
    if (writer) {
        const uint32_t r   = (uint32_t)tid;
        const uint32_t off = (uint32_t)rank * 64u;
        dst_h[0] = mapa_(s2u(&h_s[0][0]), r) + off;
        dst_h[1] = mapa_(s2u(&h_s[1][0]), r) + off;
        dst_m[0] = mapa_(s2u(&mbar[0]), r);
        dst_m[1] = mapa_(s2u(&mbar[1]), r);
    }
    const uint32_t stage_a[2] = { s2u(&h_stage[0][0]), s2u(&h_stage[1][0]) };

    const uint32_t mb0 = s2u(&mbar[0]);
    const uint32_t mb1 = s2u(&mbar[1]);
    if (tid == 0) {
        MBAR_INIT(mb0, 1);
        MBAR_INIT(mb1, 1);
        MBAR_EXPECT_TX(mb0, 1024);
        MBAR_EXPECT_TX(mb1, 1024);
    }
    __syncthreads();
    cluster_sync_();

    const int zbase = dir * 1024 + (int)rank * 16 + jj;
    uint32_t ph0 = 0, ph1 = 0;

    // Software pipeline: z for step 0 loaded before the loop.
    float zi = 0.f, zf = 0.f, zg = 0.f, zo = 0.f;
    if (writer) {
        const int t0 = dir ? (TT - 1) : 0;
        const float* zr = g_zin + (size_t)t0 * RTOT + zbase;
        zi = zr[0]; zf = zr[256]; zg = zr[512]; zo = zr[768];
    }

    for (int s = 0; s < TT; s++) {
        const int t = dir ? (TT - 1 - s) : s;
        const int b = s & 1;

        // Prefetch NEXT step's z before the wait.
        float nzi = 0.f, nzf = 0.f, nzg = 0.f, nzo = 0.f;
        if (s + 1 < TT && writer) {
            const int tn = dir ? (TT - 2 - s) : (s + 1);
            const float* zr = g_zin + (size_t)tn * RTOT + zbase;
            nzi = zr[0]; nzf = zr[256]; nzg = zr[512]; nzo = zr[768];
        }

        if (s > 0) {
            if (b) { mbar_wait_parity(mb1, ph1); ph1 ^= 1; if (tid == 0) MBAR_EXPECT_TX(mb1, 1024); }
            else   { mbar_wait_parity(mb0, ph0); ph0 ^= 1; if (tid == 0) MBAR_EXPECT_TX(mb0, 1024); }
        }

        // matvec partial: 32 packed f32x2 FMAs, raw partial straight to smem.
        const ulonglong2* hp = (const ulonglong2*)&h_s[b][q * 64];
        unsigned long long a0 = 0ull, a1 = 0ull;
#pragma unroll
        for (int k = 0; k < 16; k++) {
            const int m = (k + 2 * q) & 15;
            const ulonglong2 hv = hp[m];
            a0 = ffma2(w2[2 * k],     hv.x, a0);
            a1 = ffma2(w2[2 * k + 1], hv.y, a1);
        }
        z_s[lr][q] = (lo32(a0) + hi32(a0)) + (lo32(a1) + hi32(a1));
        __syncthreads();

        if (writer) {
            const float4 pi = *(const float4*)&z_s[jj][0];
            const float4 pf = *(const float4*)&z_s[16 + jj][0];
            const float4 pg = *(const float4*)&z_s[32 + jj][0];
            const float4 po = *(const float4*)&z_s[48 + jj][0];
            const float xi = ((pi.x + pi.y) + (pi.z + pi.w)) + zi;
            const float xf = ((pf.x + pf.y) + (pf.z + pf.w)) + zf;
            const float xg = ((pg.x + pg.y) + (pg.z + pg.w)) + zg;
            const float xo = ((po.x + po.y) + (po.z + po.w)) + zo;
            const float ig = fsigm(xi);
            const float fg = fsigm(xf);
            const float gg = tanh_ap(xg);
            const float og = fsigm(xo);
            c_reg = fg * c_reg + ig * gg;
            const float h = og * tanh_ap(c_reg);

            g_hs[(size_t)t * 512 + dir * H2D + (int)rank * 16 + jj] = h;

            if (s != TT - 1) {
                const int nb = b ^ 1;
                // stage own slice (double-buffered: async copies of step s-1
                // may still be reading the other stage buffer)
                h_stage[b][jj] = h;
                __syncwarp(0x0000FFFFu);
                fence_proxy_async_();
                // one 64-B bulk copy per lane -> rank = lane
                bulk_copy64(dst_h[nb], stage_a[b], dst_m[nb]);
            }
        }
        zi = nzi; zf = nzf; zg = nzg; zo = nzo;
    }
}

// ---------------------------------------------------------------------------
// Kernel 3: logits = hs @ w_lin^T + b_lin.  One warp per timestep.
// ---------------------------------------------------------------------------
__global__ __launch_bounds__(256) void linear_kernel(
    const float* __restrict__ wlin, const float* __restrict__ blin)
{
    const int warp = threadIdx.x >> 5;
    const int lane = threadIdx.x & 31;
    const int t = blockIdx.x * 8 + warp;

    const float4* hrow = (const float4*)(g_hs + (size_t)t * 512);
    const float4* wrow = (const float4*)(wlin + (size_t)lane * 512);
    float acc = blin[lane];
#pragma unroll 8
    for (int m = 0; m < 128; m++) {
        const float4 h4 = hrow[m];
        const float4 w4 = wrow[m];
        acc += h4.x * w4.x + h4.y * w4.y + h4.z * w4.z + h4.w * w4.w;
    }
    g_logits[(size_t)t * LDIM + lane] = acc;
}

// ---------------------------------------------------------------------------
// Kernel 4a: CRF chunk matrices (parallel).
// ---------------------------------------------------------------------------
__global__ __launch_bounds__(1024) void crf_chunk_kernel(const float* __restrict__ trans)
{
    __shared__ float Mbuf[2][32][33];
    __shared__ float rmax[32];

    const int tid = threadIdx.x;
    const int n = tid >> 5;
    const int p = tid & 31;
    const int t0 = blockIdx.x * CLEN;

    float Erow[32];
#pragma unroll
    for (int k = 0; k < 32; k++) Erow[k] = __expf(trans[n * 32 + k]);

    Mbuf[0][n][p] = (n == p) ? 1.f : 0.f;
    __syncthreads();

    float lsc = 0.f;
#pragma unroll 1
    for (int i = 0; i < CLEN; i++) {
        const int rb = i & 1, wb = rb ^ 1;
        const float e = __expf(g_logits[(size_t)(t0 + i) * LDIM + n]);
        float acc = 0.f;
#pragma unroll
        for (int k = 0; k < 32; k++) acc += Erow[k] * Mbuf[rb][k][p];
        acc *= e;

        float m = acc;
#pragma unroll
        for (int o = 16; o; o >>= 1) m = fmaxf(m, __shfl_xor_sync(0xffffffffu, m, o));
        if (p == 0) rmax[n] = m;
        __syncthreads();
        float gm = rmax[0];
#pragma unroll
        for (int k = 1; k < 32; k++) gm = fmaxf(gm, rmax[k]);

        Mbuf[wb][n][p] = acc * __frcp_rn(gm);
        lsc += __logf(gm);
        __syncthreads();
    }

    g_P[(size_t)blockIdx.x * 1024 + n * 32 + p] = Mbuf[CLEN & 1][n][p];
    if (tid == 0) g_lsc[blockIdx.x] = lsc;
}

// ---------------------------------------------------------------------------
// Kernel 4b: CRF final combine + gold path.
// ---------------------------------------------------------------------------
__global__ void crf_final_kernel(const float* __restrict__ trans,
                                 const int* __restrict__ target,
                                 float* __restrict__ out)
{
    __shared__ float tr_s[32 * 33];
    __shared__ float beta[32];
    __shared__ float gold_s;

    const int tid  = threadIdx.x;   // blockDim = 64
    const int warp = tid >> 5;
    const int lane = tid & 31;

    for (int i = tid; i < 1024; i += 64) {
        const int n = i >> 5, p = i & 31;
        tr_s[n * 33 + p] = trans[i];
    }
    __syncthreads();

    if (warp == 1) {
        float gs = 0.f;
        for (int t = lane; t < TT; t += 32) {
            const int nxt  = target[t];
            const int prev = (t == 0) ? 0 : target[t - 1];
            gs += tr_s[nxt * 33 + prev] + g_logits[(size_t)t * LDIM + nxt];
        }
#pragma unroll
        for (int o = 16; o; o >>= 1) gs += __shfl_xor_sync(0xffffffffu, gs, o);
        gs += tr_s[31 * 33 + target[TT - 1]];
        if (lane == 0) gold_s = gs;
    } else {
        float lsc = 0.f;
#pragma unroll
        for (int i = 0; i < 4; i++) lsc += g_lsc[lane + 32 * i];
#pragma unroll
        for (int o = 16; o; o >>= 1) lsc += __shfl_xor_sync(0xffffffffu, lsc, o);

        beta[lane] = (lane == 0) ? 1.f : 0.f;
        __syncwarp();

        float4 pr[8];
#pragma unroll
        for (int j = 0; j < 8; j++)
            pr[j] = ((const float4*)(g_P + (size_t)lane * 32))[j];

        for (int c = 0; c < NCHUNK; c++) {
            float4 cur[8];
#pragma unroll
            for (int j = 0; j < 8; j++) cur[j] = pr[j];
            if (c < NCHUNK - 1) {
#pragma unroll
                for (int j = 0; j < 8; j++)
                    pr[j] = ((const float4*)(g_P + (size_t)(c + 1) * 1024 + lane * 32))[j];
            }
            float acc = 0.f;
#pragma unroll
            for (int j = 0; j < 8; j++) {
                acc += cur[j].x * beta[4 * j + 0];
                acc += cur[j].y * beta[4 * j + 1];
                acc += cur[j].z * beta[4 * j + 2];
                acc += cur[j].w * beta[4 * j + 3];
            }
            float m = acc;
#pragma unroll
            for (int o = 16; o; o >>= 1) m = fmaxf(m, __shfl_xor_sync(0xffffffffu, m, o));
            lsc += __logf(m);
            __syncwarp();
            beta[lane] = acc * __frcp_rn(m);
            __syncwarp();
        }

        float v = beta[lane] * __expf(tr_s[31 * 33 + lane]);
#pragma unroll
        for (int o = 16; o; o >>= 1) v += __shfl_xor_sync(0xffffffffu, v, o);
        const float fwd = __logf(v) + lsc;
        if (lane == 0) beta[0] = fwd;
    }

    __syncthreads();
    if (tid == 0) out[0] = beta[0] - gold_s;
}

// ---------------------------------------------------------------------------
// Launch.  lstm_kernel stays at captured launch index 3.
// ---------------------------------------------------------------------------
extern "C" void kernel_launch(void* const* d_in, const int* in_sizes, int n_in,
                              void* d_out, int out_size)
{
    const int*   ids    = (const int*)  d_in[0];
    const int*   target = (const int*)  d_in[2];
    const float* emb    = (const float*)d_in[3];
    const float* wihf   = (const float*)d_in[4];
    const float* whhf   = (const float*)d_in[5];
    const float* bf     = (const float*)d_in[6];
    const float* wihb   = (const float*)d_in[7];
    const float* whhb   = (const float*)d_in[8];
    const float* bb     = (const float*)d_in[9];
    const float* wlin   = (const float*)d_in[10];
    const float* blin   = (const float*)d_in[11];
    const float* trans  = (const float*)d_in[12];
    const float* h0     = (const float*)d_in[13];
    const float* c0     = (const float*)d_in[14];

    cudaFuncSetAttribute(lstm_kernel, cudaFuncAttributeNonPortableClusterSizeAllowed, 1);

    dim3 g1(RTOT / 64, TT / 64);
    zin_kernel<<<g1, 256>>>(ids, emb, wihf, wihb, bf, bb);   // idx 0
    dummy_kernel<<<1, 32>>>();                               // idx 1
    dummy_kernel<<<1, 32>>>();                               // idx 2
    lstm_kernel<<<32, 256>>>(whhf, whhb, h0, c0);            // idx 3  <- ncu capture
    linear_kernel<<<TT / 8, 256>>>(wlin, blin);
    crf_chunk_kernel<<<NCHUNK, 1024>>>(trans);
    crf_final_kernel<<<1, 64>>>(trans, target, (float*)d_out);
}

// round 11
// speedup vs baseline: 1.0252x; 1.0252x over previous
#include <cuda_runtime.h>
#include <cuda_bf16.h>
#include <cstdint>
#include <math.h>

// ---------------------------------------------------------------------------
// Problem constants
// ---------------------------------------------------------------------------
#define TT   2048
#define EDIM 256
#define H2D  256
#define LDIM 32
#define RTOT 2048   // 2 dirs * 4 gates * 256
#define NCHUNK 128
#define CLEN   16   // CRF steps per chunk

// ---------------------------------------------------------------------------
// Scratch
// ---------------------------------------------------------------------------
__device__ float g_zin[TT * RTOT];        // 16 MB (L2-resident)
__device__ float g_hs[TT * 512];          // 4 MB
__device__ float g_logits[TT * LDIM];     // 256 KB
__device__ float g_P[NCHUNK * 1024];      // 512 KB
__device__ float g_lsc[NCHUNK];

// ---------------------------------------------------------------------------
// Helpers
// ---------------------------------------------------------------------------
__device__ __forceinline__ uint32_t s2u(const void* p) {
    uint32_t a;
    asm("{ .reg .u64 t; cvta.to.shared.u64 t, %1; cvt.u32.u64 %0, t; }"
        : "=r"(a) : "l"(p));
    return a;
}
__device__ __forceinline__ void cluster_sync_() {
    asm volatile("barrier.cluster.arrive.aligned;\n\t"
                 "barrier.cluster.wait.aligned;" ::: "memory");
}
__device__ __forceinline__ uint32_t my_ctarank() {
    uint32_t r;
    asm("mov.u32 %0, %%cluster_ctarank;" : "=r"(r));
    return r;
}
__device__ __forceinline__ uint32_t mapa_(uint32_t a, uint32_t r) {
    uint32_t d;
    asm("mapa.shared::cluster.u32 %0, %1, %2;" : "=r"(d) : "r"(a), "r"(r));
    return d;
}
__device__ __forceinline__ unsigned long long ffma2(unsigned long long a,
                                                    unsigned long long b,
                                                    unsigned long long c) {
    unsigned long long d;
    asm("fma.rn.f32x2 %0, %1, %2, %3;" : "=l"(d) : "l"(a), "l"(b), "l"(c));
    return d;
}
__device__ __forceinline__ float lo32(unsigned long long v) { return __uint_as_float((unsigned)v); }
__device__ __forceinline__ float hi32(unsigned long long v) { return __uint_as_float((unsigned)(v >> 32)); }

__device__ __forceinline__ void st_async_f32(uint32_t daddr, float v, uint32_t dmbar) {
    asm volatile("st.async.shared::cluster.mbarrier::complete_tx::bytes.f32 [%0], %1, [%2];"
                 :: "r"(daddr), "f"(v), "r"(dmbar) : "memory");
}

#define MBAR_INIT(a, n) \
    asm volatile("mbarrier.init.shared.b64 [%0], %1;" :: "r"(a), "r"((uint32_t)(n)) : "memory")
#define MBAR_EXPECT_TX(a, n) \
    asm volatile("mbarrier.arrive.expect_tx.shared.b64 _, [%0], %1;" :: "r"(a), "r"((uint32_t)(n)) : "memory")

__device__ __forceinline__ void mbar_wait_parity(uint32_t mbar, uint32_t parity) {
    uint32_t done;
    asm volatile(
        "{\n\t.reg .pred p;\n\t"
        "mbarrier.try_wait.parity.acquire.cta.shared::cta.b64 p, [%1], %2;\n\t"
        "selp.b32 %0, 1, 0, p;\n\t}"
        : "=r"(done) : "r"(mbar), "r"(parity) : "memory");
    if (!done) {
        asm volatile(
            "{\n\t.reg .pred P1;\n\t"
            "WL_%=:\n\t"
            "mbarrier.try_wait.parity.acquire.cta.shared::cta.b64 P1, [%0], %1, 0x989680;\n\t"
            "@P1 bra.uni WD_%=;\n\t"
            "bra.uni WL_%=;\n\t"
            "WD_%=:\n\t}"
            :: "r"(mbar), "r"(parity) : "memory");
    }
}

// Fast activations (rel_err 0.0 proven over 2048 steps)
__device__ __forceinline__ float tanh_ap(float x) {
    float y;
    asm("tanh.approx.f32 %0, %1;" : "=f"(y) : "f"(x));
    return y;
}

// ---------------------------------------------------------------------------
// Dummy kernel: keeps lstm_kernel at captured launch index 3.
// ---------------------------------------------------------------------------
__global__ void dummy_kernel() {}

// ---------------------------------------------------------------------------
// Kernel 1: Zin[t][col] = emb[ids[t]] @ Wih^T + b
// ---------------------------------------------------------------------------
__global__ __launch_bounds__(256) void zin_kernel(
    const int* __restrict__ ids, const float* __restrict__ emb,
    const float* __restrict__ wihf, const float* __restrict__ wihb,
    const float* __restrict__ bf, const float* __restrict__ bb)
{
    __shared__ float As[32][68];
    __shared__ float Bs[32][68];
    __shared__ int gids[64];

    const int tid = threadIdx.x;
    const int tx = tid & 15;
    const int ty = tid >> 4;
    const int tRow = blockIdx.y * 64;
    const int nCol = blockIdx.x * 64;

    if (tid < 64) gids[tid] = ids[tRow + tid];
    __syncthreads();

    float acc[4][4];
#pragma unroll
    for (int i = 0; i < 4; i++)
#pragma unroll
        for (int j = 0; j < 4; j++) acc[i][j] = 0.f;

    for (int kk = 0; kk < EDIM; kk += 32) {
#pragma unroll
        for (int u = 0; u < 2; u++) {
            int idx = tid + u * 256;
            int row = idx >> 3;
            int c4  = (idx & 7) * 4;
            const float4 av = *(const float4*)(emb + (size_t)gids[row] * EDIM + kk + c4);
            As[c4 + 0][row] = av.x; As[c4 + 1][row] = av.y;
            As[c4 + 2][row] = av.z; As[c4 + 3][row] = av.w;
            int brow = nCol + row;
            const float* bp = (brow < 1024)
                ? (wihf + (size_t)brow * EDIM)
                : (wihb + (size_t)(brow - 1024) * EDIM);
            const float4 bv = *(const float4*)(bp + kk + c4);
            Bs[c4 + 0][row] = bv.x; Bs[c4 + 1][row] = bv.y;
            Bs[c4 + 2][row] = bv.z; Bs[c4 + 3][row] = bv.w;
        }
        __syncthreads();
#pragma unroll
        for (int k = 0; k < 32; k++) {
            const float4 av = *(const float4*)&As[k][ty * 4];
            const float4 bv = *(const float4*)&Bs[k][tx * 4];
            const float ar[4] = {av.x, av.y, av.z, av.w};
            const float br[4] = {bv.x, bv.y, bv.z, bv.w};
#pragma unroll
            for (int i = 0; i < 4; i++)
#pragma unroll
                for (int j = 0; j < 4; j++) acc[i][j] += ar[i] * br[j];
        }
        __syncthreads();
    }

    const int colBase = nCol + tx * 4;
    float bias[4];
#pragma unroll
    for (int j = 0; j < 4; j++) {
        int c = colBase + j;
        bias[j] = (c < 1024) ? bf[c] : bb[c - 1024];
    }
#pragma unroll
    for (int i = 0; i < 4; i++) {
        int row = tRow + ty * 4 + i;
        float4 o;
        o.x = acc[i][0] + bias[0];
        o.y = acc[i][1] + bias[1];
        o.z = acc[i][2] + bias[2];
        o.w = acc[i][3] + bias[3];
        *(float4*)(g_zin + (size_t)row * RTOT + colBase) = o;
    }
}

// ---------------------------------------------------------------------------
// Kernel 2: BiLSTM recurrence. 2 clusters of 16 CTAs (fwd / bwd).
// Warp-autonomous: warp w owns jj in {2w, 2w+1}; no intra-CTA barrier.
// Lane (jp = l>>4, gate = (l>>2)&3, q = l&3). Messaging: 1 st.async per lane
// (proven scheme, 256 msgs/CTA/step). Activations: 2 MUFU per warp total.
// ---------------------------------------------------------------------------
__global__ void __launch_bounds__(256, 1) __cluster_dims__(16, 1, 1)
lstm_kernel(const float* __restrict__ whhf, const float* __restrict__ whhb,
            const float* __restrict__ h0, const float* __restrict__ c0)
{
    __shared__ __align__(128) float h_s[2][256];
    __shared__ unsigned long long mbar[2];

    const int tid  = threadIdx.x;
    const int w    = tid >> 5;
    const int lane = tid & 31;
    const int dir  = blockIdx.x >> 4;
    const uint32_t rank = my_ctarank();

    const int jp   = lane >> 4;          // which of the warp's two jj
    const int gate = (lane >> 2) & 3;    // 0:i 1:f 2:g 3:o
    const int q    = lane & 3;           // 64-col quarter
    const int jj   = 2 * w + jp;         // 0..15
    const int grow = gate * 256 + (int)rank * 16 + jj;

    const float* whh = dir ? whhb : whhf;

    unsigned long long w2[32];
    {
        const float* wr = whh + (size_t)grow * H2D + q * 64;
#pragma unroll
        for (int k = 0; k < 16; k++) {
            int m = (k + 2 * q) & 15;
            const unsigned long long* p = (const unsigned long long*)(wr + m * 4);
            w2[2 * k]     = p[0];
            w2[2 * k + 1] = p[1];
        }
    }

    const bool is_q0     = (q == 0);
    const bool is_writer = ((lane & 15) == 0);   // lanes 0, 16

    float c_reg = 0.f;
    if (is_writer) c_reg = c0[dir * H2D + (int)rank * 16 + jj];

    h_s[0][tid] = h0[dir * H2D + tid];

    // Send targets: every lane sends h(jj) to rank = lane & 15.
    const uint32_t drank = (uint32_t)(lane & 15);
    const uint32_t off   = 4u * ((uint32_t)rank * 16 + (uint32_t)jj);
    const uint32_t dst_h[2] = { mapa_(s2u(&h_s[0][0]), drank) + off,
                                mapa_(s2u(&h_s[1][0]), drank) + off };
    const uint32_t dst_m[2] = { mapa_(s2u(&mbar[0]), drank),
                                mapa_(s2u(&mbar[1]), drank) };

    const uint32_t mb[2] = { s2u(&mbar[0]), s2u(&mbar[1]) };
    if (tid == 0) {
        MBAR_INIT(mb[0], 1);
        MBAR_INIT(mb[1], 1);
        MBAR_EXPECT_TX(mb[0], 1024);
        MBAR_EXPECT_TX(mb[1], 1024);
    }
    __syncthreads();
    cluster_sync_();

    // z-input loader lanes: q==0 (8 per warp), one float each per step.
    const int zidx = dir * 1024 + grow;    // g_zin column for (gate, jj)
    uint32_t ph[2] = { 0, 0 };

    float zv = 0.f;
    if (is_q0) {
        const int t0 = dir ? (TT - 1) : 0;
        zv = g_zin[(size_t)t0 * RTOT + zidx];
    }

    for (int s = 0; s < TT; s++) {
        const int t = dir ? (TT - 1 - s) : s;
        const int b = s & 1;

        // prefetch next step's z (8 lanes/warp, 64 LDG/CTA)
        float nzv = 0.f;
        if (s + 1 < TT && is_q0) {
            const int tn = dir ? (TT - 2 - s) : (s + 1);
            nzv = g_zin[(size_t)tn * RTOT + zidx];
        }

        if (s > 0) { mbar_wait_parity(mb[b], ph[b]); ph[b] ^= 1; if (tid == 0) MBAR_EXPECT_TX(mb[b], 1024); }

        // matvec partial: 32 packed f32x2 FMAs over own 64-col quarter
        const ulonglong2* hp = (const ulonglong2*)&h_s[b][q * 64];
        unsigned long long a0 = 0ull, a1 = 0ull;
#pragma unroll
        for (int k = 0; k < 16; k++) {
            const int m = (k + 2 * q) & 15;
            const ulonglong2 hv = hp[m];
            a0 = ffma2(w2[2 * k],     hv.x, a0);
            a1 = ffma2(w2[2 * k + 1], hv.y, a1);
        }
        float part = (lo32(a0) + hi32(a0)) + (lo32(a1) + hi32(a1));
        part += __shfl_xor_sync(0xffffffffu, part, 1);
        part += __shfl_xor_sync(0xffffffffu, part, 2);
        // q==0 lanes now hold full matvec for (gate, jj); add z input
        const float x = part + zv;

        // Single-MUFU activation for all gates: sigmoid via tanh(x/2) scaling
        const bool sig = (gate != 2);
        const float arg = sig ? 0.5f * x : x;
        const float y   = tanh_ap(arg);
        const float act = sig ? __fmaf_rn(0.5f, y, 0.5f) : y;

        // Writer lanes gather f, g, o acts (independent shfls) and update c
        const int base = lane & 16;
        const float af = __shfl_sync(0xffffffffu, act, base + 4);
        const float ag = __shfl_sync(0xffffffffu, act, base + 8);
        const float ao = __shfl_sync(0xffffffffu, act, base + 12);
        float h = 0.f;
        if (is_writer) {
            c_reg = af * c_reg + act * ag;      // act on lane base+0 is gate i
            h = ao * tanh_ap(c_reg);
        }
        // broadcast h(jj) to all 16 lanes of the half-warp
        const float hb = __shfl_sync(0xffffffffu, h, base);

        if (s != TT - 1) {
            const int nb = b ^ 1;
            st_async_f32(dst_h[nb], hb, dst_m[nb]);
        }
        if (is_writer)
            g_hs[(size_t)t * 512 + dir * H2D + (int)rank * 16 + jj] = h;

        zv = nzv;
    }
}

// ---------------------------------------------------------------------------
// Kernel 3: logits = hs @ w_lin^T + b_lin.  One warp per timestep.
// 4 independent accumulators to break the serial FFMA chain.
// ---------------------------------------------------------------------------
__global__ __launch_bounds__(256) void linear_kernel(
    const float* __restrict__ wlin, const float* __restrict__ blin)
{
    const int warp = threadIdx.x >> 5;
    const int lane = threadIdx.x & 31;
    const int t = blockIdx.x * 8 + warp;

    const float4* hrow = (const float4*)(g_hs + (size_t)t * 512);
    const float4* wrow = (const float4*)(wlin + (size_t)lane * 512);
    float s0 = 0.f, s1 = 0.f, s2 = 0.f, s3 = 0.f;
#pragma unroll 8
    for (int m = 0; m < 128; m += 4) {
        const float4 h0v = hrow[m],     w0v = wrow[m];
        const float4 h1v = hrow[m + 1], w1v = wrow[m + 1];
        const float4 h2v = hrow[m + 2], w2v = wrow[m + 2];
        const float4 h3v = hrow[m + 3], w3v = wrow[m + 3];
        s0 += h0v.x * w0v.x + h0v.y * w0v.y + h0v.z * w0v.z + h0v.w * w0v.w;
        s1 += h1v.x * w1v.x + h1v.y * w1v.y + h1v.z * w1v.z + h1v.w * w1v.w;
        s2 += h2v.x * w2v.x + h2v.y * w2v.y + h2v.z * w2v.z + h2v.w * w2v.w;
        s3 += h3v.x * w3v.x + h3v.y * w3v.y + h3v.z * w3v.z + h3v.w * w3v.w;
    }
    g_logits[(size_t)t * LDIM + lane] = ((s0 + s1) + (s2 + s3)) + blin[lane];
}

// ---------------------------------------------------------------------------
// Kernel 4a: CRF chunk matrices (parallel).
// ---------------------------------------------------------------------------
__global__ __launch_bounds__(1024) void crf_chunk_kernel(const float* __restrict__ trans)
{
    __shared__ float Mbuf[2][32][33];
    __shared__ float rmax[32];

    const int tid = threadIdx.x;
    const int n = tid >> 5;
    const int p = tid & 31;
    const int t0 = blockIdx.x * CLEN;

    float Erow[32];
#pragma unroll
    for (int k = 0; k < 32; k++) Erow[k] = __expf(trans[n * 32 + k]);

    Mbuf[0][n][p] = (n == p) ? 1.f : 0.f;
    __syncthreads();

    float lsc = 0.f;
#pragma unroll 1
    for (int i = 0; i < CLEN; i++) {
        const int rb = i & 1, wb = rb ^ 1;
        const float e = __expf(g_logits[(size_t)(t0 + i) * LDIM + n]);
        float acc = 0.f;
#pragma unroll
        for (int k = 0; k < 32; k++) acc += Erow[k] * Mbuf[rb][k][p];
        acc *= e;

        float m = acc;
#pragma unroll
        for (int o = 16; o; o >>= 1) m = fmaxf(m, __shfl_xor_sync(0xffffffffu, m, o));
        if (p == 0) rmax[n] = m;
        __syncthreads();
        float gm = rmax[0];
#pragma unroll
        for (int k = 1; k < 32; k++) gm = fmaxf(gm, rmax[k]);

        Mbuf[wb][n][p] = acc * __frcp_rn(gm);
        lsc += __logf(gm);
        __syncthreads();
    }

    g_P[(size_t)blockIdx.x * 1024 + n * 32 + p] = Mbuf[CLEN & 1][n][p];
    if (tid == 0) g_lsc[blockIdx.x] = lsc;
}

// ---------------------------------------------------------------------------
// Kernel 4b: CRF final combine + gold path.
// ---------------------------------------------------------------------------
__global__ void crf_final_kernel(const float* __restrict__ trans,
                                 const int* __restrict__ target,
                                 float* __restrict__ out)
{
    __shared__ float tr_s[32 * 33];
    __shared__ float beta[32];
    __shared__ float gold_s;

    const int tid  = threadIdx.x;   // blockDim = 64
    const int warp = tid >> 5;
    const int lane = tid & 31;

    for (int i = tid; i < 1024; i += 64) {
        const int n = i >> 5, p = i & 31;
        tr_s[n * 33 + p] = trans[i];
    }
    __syncthreads();

    if (warp == 1) {
        float gs = 0.f;
        for (int t = lane; t < TT; t += 32) {
            const int nxt  = target[t];
            const int prev = (t == 0) ? 0 : target[t - 1];
            gs += tr_s[nxt * 33 + prev] + g_logits[(size_t)t * LDIM + nxt];
        }
#pragma unroll
        for (int o = 16; o; o >>= 1) gs += __shfl_xor_sync(0xffffffffu, gs, o);
        gs += tr_s[31 * 33 + target[TT - 1]];
        if (lane == 0) gold_s = gs;
    } else {
        float lsc = 0.f;
#pragma unroll
        for (int i = 0; i < 4; i++) lsc += g_lsc[lane + 32 * i];
#pragma unroll
        for (int o = 16; o; o >>= 1) lsc += __shfl_xor_sync(0xffffffffu, lsc, o);

        beta[lane] = (lane == 0) ? 1.f : 0.f;
        __syncwarp();

        float4 pr[8];
#pragma unroll
        for (int j = 0; j < 8; j++)
            pr[j] = ((const float4*)(g_P + (size_t)lane * 32))[j];

        for (int c = 0; c < NCHUNK; c++) {
            float4 cur[8];
#pragma unroll
            for (int j = 0; j < 8; j++) cur[j] = pr[j];
            if (c < NCHUNK - 1) {
#pragma unroll
                for (int j = 0; j < 8; j++)
                    pr[j] = ((const float4*)(g_P + (size_t)(c + 1) * 1024 + lane * 32))[j];
            }
            float acc = 0.f;
#pragma unroll
            for (int j = 0; j < 8; j++) {
                acc += cur[j].x * beta[4 * j + 0];
                acc += cur[j].y * beta[4 * j + 1];
                acc += cur[j].z * beta[4 * j + 2];
                acc += cur[j].w * beta[4 * j + 3];
            }
            float m = acc;
#pragma unroll
            for (int o = 16; o; o >>= 1) m = fmaxf(m, __shfl_xor_sync(0xffffffffu, m, o));
            lsc += __logf(m);
            __syncwarp();
            beta[lane] = acc * __frcp_rn(m);
            __syncwarp();
        }

        float v = beta[lane] * __expf(tr_s[31 * 33 + lane]);
#pragma unroll
        for (int o = 16; o; o >>= 1) v += __shfl_xor_sync(0xffffffffu, v, o);
        const float fwd = __logf(v) + lsc;
        if (lane == 0) beta[0] = fwd;
    }

    __syncthreads();
    if (tid == 0) out[0] = beta[0] - gold_s;
}

// ---------------------------------------------------------------------------
// Launch.  lstm_kernel stays at captured launch index 3.
// ---------------------------------------------------------------------------
extern "C" void kernel_launch(void* const* d_in, const int* in_sizes, int n_in,
                              void* d_out, int out_size)
{
    const int*   ids    = (const int*)  d_in[0];
    const int*   target = (const int*)  d_in[2];
    const float* emb    = (const float*)d_in[3];
    const float* wihf   = (const float*)d_in[4];
    const float* whhf   = (const float*)d_in[5];
    const float* bf     = (const float*)d_in[6];
    const float* wihb   = (const float*)d_in[7];
    const float* whhb   = (const float*)d_in[8];
    const float* bb     = (const float*)d_in[9];
    const float* wlin   = (const float*)d_in[10];
    const float* blin   = (const float*)d_in[11];
    const float* trans  = (const float*)d_in[12];
    const float* h0     = (const float*)d_in[13];
    const float* c0     = (const float*)d_in[14];

    cudaFuncSetAttribute(lstm_kernel, cudaFuncAttributeNonPortableClusterSizeAllowed, 1);

    dim3 g1(RTOT / 64, TT / 64);
    zin_kernel<<<g1, 256>>>(ids, emb, wihf, wihb, bf, bb);   // idx 0
    dummy_kernel<<<1, 32>>>();                               // idx 1
    dummy_kernel<<<1, 32>>>();                               // idx 2
    lstm_kernel<<<32, 256>>>(whhf, whhb, h0, c0);            // idx 3  <- ncu capture
    linear_kernel<<<TT / 8, 256>>>(wlin, blin);
    crf_chunk_kernel<<<NCHUNK, 1024>>>(trans);
    crf_final_kernel<<<1, 64>>>(trans, target, (float*)d_out);
}

// round 12
// speedup vs baseline: 1.5398x; 1.5020x over previous
#include <cuda_runtime.h>
#include <cuda_bf16.h>
#include <cstdint>
#include <math.h>

// ---------------------------------------------------------------------------
// Problem constants
// ---------------------------------------------------------------------------
#define TT   2048
#define EDIM 256
#define H2D  256
#define LDIM 32
#define RTOT 2048   // 2 dirs * 4 gates * 256
#define NCHUNK 128
#define CLEN   16   // CRF steps per chunk

// ---------------------------------------------------------------------------
// Scratch
// ---------------------------------------------------------------------------
__device__ float g_zin[TT * RTOT];        // 16 MB (L2-resident)
__device__ float g_hs[TT * 512];          // 4 MB
__device__ float g_logits[TT * LDIM];     // 256 KB
__device__ float g_P[NCHUNK * 1024];      // 512 KB
__device__ float g_lsc[NCHUNK];

// ---------------------------------------------------------------------------
// Helpers
// ---------------------------------------------------------------------------
__device__ __forceinline__ uint32_t s2u(const void* p) {
    uint32_t a;
    asm("{ .reg .u64 t; cvta.to.shared.u64 t, %1; cvt.u32.u64 %0, t; }"
        : "=r"(a) : "l"(p));
    return a;
}
__device__ __forceinline__ void cluster_sync_() {
    asm volatile("barrier.cluster.arrive.aligned;\n\t"
                 "barrier.cluster.wait.aligned;" ::: "memory");
}
__device__ __forceinline__ uint32_t my_ctarank() {
    uint32_t r;
    asm("mov.u32 %0, %%cluster_ctarank;" : "=r"(r));
    return r;
}
__device__ __forceinline__ uint32_t mapa_(uint32_t a, uint32_t r) {
    uint32_t d;
    asm("mapa.shared::cluster.u32 %0, %1, %2;" : "=r"(d) : "r"(a), "r"(r));
    return d;
}
__device__ __forceinline__ unsigned long long ffma2(unsigned long long a,
                                                    unsigned long long b,
                                                    unsigned long long c) {
    unsigned long long d;
    asm("fma.rn.f32x2 %0, %1, %2, %3;" : "=l"(d) : "l"(a), "l"(b), "l"(c));
    return d;
}
__device__ __forceinline__ float lo32(unsigned long long v) { return __uint_as_float((unsigned)v); }
__device__ __forceinline__ float hi32(unsigned long long v) { return __uint_as_float((unsigned)(v >> 32)); }

__device__ __forceinline__ void st_async_f32(uint32_t daddr, float v, uint32_t dmbar) {
    asm volatile("st.async.shared::cluster.mbarrier::complete_tx::bytes.f32 [%0], %1, [%2];"
                 :: "r"(daddr), "f"(v), "r"(dmbar) : "memory");
}

#define MBAR_INIT(a, n) \
    asm volatile("mbarrier.init.shared.b64 [%0], %1;" :: "r"(a), "r"((uint32_t)(n)) : "memory")
#define MBAR_EXPECT_TX(a, n) \
    asm volatile("mbarrier.arrive.expect_tx.shared.b64 _, [%0], %1;" :: "r"(a), "r"((uint32_t)(n)) : "memory")

__device__ __forceinline__ void mbar_wait_parity(uint32_t mbar, uint32_t parity) {
    uint32_t done;
    asm volatile(
        "{\n\t.reg .pred p;\n\t"
        "mbarrier.try_wait.parity.acquire.cta.shared::cta.b64 p, [%1], %2;\n\t"
        "selp.b32 %0, 1, 0, p;\n\t}"
        : "=r"(done) : "r"(mbar), "r"(parity) : "memory");
    if (!done) {
        asm volatile(
            "{\n\t.reg .pred P1;\n\t"
            "WL_%=:\n\t"
            "mbarrier.try_wait.parity.acquire.cta.shared::cta.b64 P1, [%0], %1, 0x989680;\n\t"
            "@P1 bra.uni WD_%=;\n\t"
            "bra.uni WL_%=;\n\t"
            "WD_%=:\n\t}"
            :: "r"(mbar), "r"(parity) : "memory");
    }
}

// Fast activations (rel_err 0.0 proven over 2048 steps)
__device__ __forceinline__ float tanh_ap(float x) {
    float y;
    asm("tanh.approx.f32 %0, %1;" : "=f"(y) : "f"(x));
    return y;
}
__device__ __forceinline__ float fsigm(float x) {
    return __fmaf_rn(0.5f, tanh_ap(0.5f * x), 0.5f);
}

// ---------------------------------------------------------------------------
// Kernel 1: Zin[t][col] = emb[ids[t]] @ Wih^T + b
// ---------------------------------------------------------------------------
__global__ __launch_bounds__(256) void zin_kernel(
    const int* __restrict__ ids, const float* __restrict__ emb,
    const float* __restrict__ wihf, const float* __restrict__ wihb,
    const float* __restrict__ bf, const float* __restrict__ bb)
{
    __shared__ float As[32][68];
    __shared__ float Bs[32][68];
    __shared__ int gids[64];

    const int tid = threadIdx.x;
    const int tx = tid & 15;
    const int ty = tid >> 4;
    const int tRow = blockIdx.y * 64;
    const int nCol = blockIdx.x * 64;

    if (tid < 64) gids[tid] = ids[tRow + tid];
    __syncthreads();

    float acc[4][4];
#pragma unroll
    for (int i = 0; i < 4; i++)
#pragma unroll
        for (int j = 0; j < 4; j++) acc[i][j] = 0.f;

    for (int kk = 0; kk < EDIM; kk += 32) {
#pragma unroll
        for (int u = 0; u < 2; u++) {
            int idx = tid + u * 256;
            int row = idx >> 3;
            int c4  = (idx & 7) * 4;
            const float4 av = *(const float4*)(emb + (size_t)gids[row] * EDIM + kk + c4);
            As[c4 + 0][row] = av.x; As[c4 + 1][row] = av.y;
            As[c4 + 2][row] = av.z; As[c4 + 3][row] = av.w;
            int brow = nCol + row;
            const float* bp = (brow < 1024)
                ? (wihf + (size_t)brow * EDIM)
                : (wihb + (size_t)(brow - 1024) * EDIM);
            const float4 bv = *(const float4*)(bp + kk + c4);
            Bs[c4 + 0][row] = bv.x; Bs[c4 + 1][row] = bv.y;
            Bs[c4 + 2][row] = bv.z; Bs[c4 + 3][row] = bv.w;
        }
        __syncthreads();
#pragma unroll
        for (int k = 0; k < 32; k++) {
            const float4 av = *(const float4*)&As[k][ty * 4];
            const float4 bv = *(const float4*)&Bs[k][tx * 4];
            const float ar[4] = {av.x, av.y, av.z, av.w};
            const float br[4] = {bv.x, bv.y, bv.z, bv.w};
#pragma unroll
            for (int i = 0; i < 4; i++)
#pragma unroll
                for (int j = 0; j < 4; j++) acc[i][j] += ar[i] * br[j];
        }
        __syncthreads();
    }

    const int colBase = nCol + tx * 4;
    float bias[4];
#pragma unroll
    for (int j = 0; j < 4; j++) {
        int c = colBase + j;
        bias[j] = (c < 1024) ? bf[c] : bb[c - 1024];
    }
#pragma unroll
    for (int i = 0; i < 4; i++) {
        int row = tRow + ty * 4 + i;
        float4 o;
        o.x = acc[i][0] + bias[0];
        o.y = acc[i][1] + bias[1];
        o.z = acc[i][2] + bias[2];
        o.w = acc[i][3] + bias[3];
        *(float4*)(g_zin + (size_t)row * RTOT + colBase) = o;
    }
}

// ---------------------------------------------------------------------------
// Kernel 2: BiLSTM recurrence — round-9 structure (best measured: 1297us),
// with three surgical changes:
//   (a) 4-accumulator matvec (dep chain 64 -> 32 cyc)
//   (b) mbar rearm moved to warp 7 (off the writer critical path)
//   (c) DSMEM sends issued before the g_hs global store
// ---------------------------------------------------------------------------
__global__ void __launch_bounds__(256, 1) __cluster_dims__(16, 1, 1)
lstm_kernel(const float* __restrict__ whhf, const float* __restrict__ whhb,
            const float* __restrict__ h0, const float* __restrict__ c0)
{
    __shared__ __align__(128) float h_s[2][256];
    __shared__ __align__(16) float z_s[64][4];   // [gate row][column quarter]
    __shared__ unsigned long long mbar[2];

    const int tid  = threadIdx.x;
    const int dir  = blockIdx.x >> 4;
    const uint32_t rank = my_ctarank();

    const int q    = tid & 3;        // column quarter
    const int lr   = tid >> 2;       // local gate row 0..63
    const int gate = lr >> 4;
    const int jr   = lr & 15;
    const int grow = gate * 256 + (int)rank * 16 + jr;

    const float* whh = dir ? whhb : whhf;

    unsigned long long w2[32];
    {
        const float* wr = whh + (size_t)grow * H2D + q * 64;
#pragma unroll
        for (int k = 0; k < 16; k++) {
            int m = (k + 2 * q) & 15;
            const unsigned long long* p = (const unsigned long long*)(wr + m * 4);
            w2[2 * k]     = p[0];
            w2[2 * k + 1] = p[1];
        }
    }

    const int jj  = tid & 15;        // h index within this CTA's slice
    const int grp = tid >> 4;

    float c_reg = 0.f;
    if (tid < 64) c_reg = c0[dir * H2D + (int)rank * 16 + jj];

    h_s[0][tid] = h0[dir * H2D + tid];

    // Fan-out: writer (jj, grp) sends its h to ranks grp*4..grp*4+3.
    uint32_t dst_h[2][4], dst_m[2][4];
    if (tid < 64) {
        const uint32_t off = 4u * ((uint32_t)rank * 16 + (uint32_t)jj);
        const uint32_t h0a = s2u(&h_s[0][0]);
        const uint32_t h1a = s2u(&h_s[1][0]);
        const uint32_t m0a = s2u(&mbar[0]);
        const uint32_t m1a = s2u(&mbar[1]);
#pragma unroll
        for (int u = 0; u < 4; u++) {
            const uint32_t r = (uint32_t)(grp * 4 + u);
            dst_h[0][u] = mapa_(h0a, r) + off;
            dst_h[1][u] = mapa_(h1a, r) + off;
            dst_m[0][u] = mapa_(m0a, r);
            dst_m[1][u] = mapa_(m1a, r);
        }
    }

    const uint32_t mb0 = s2u(&mbar[0]);
    const uint32_t mb1 = s2u(&mbar[1]);
    if (tid == 0) {
        MBAR_INIT(mb0, 1);
        MBAR_INIT(mb1, 1);
        MBAR_EXPECT_TX(mb0, 1024);
        MBAR_EXPECT_TX(mb1, 1024);
    }
    __syncthreads();
    cluster_sync_();

    const int zbase = dir * 1024 + (int)rank * 16 + jj;
    uint32_t ph0 = 0, ph1 = 0;

    // Software pipeline: z for step 0 loaded before the loop.
    float zi = 0.f, zf = 0.f, zg = 0.f, zo = 0.f;
    if (tid < 64) {
        const int t0 = dir ? (TT - 1) : 0;
        const float* zr = g_zin + (size_t)t0 * RTOT + zbase;
        zi = zr[0]; zf = zr[256]; zg = zr[512]; zo = zr[768];
    }

    for (int s = 0; s < TT; s++) {
        const int t = dir ? (TT - 1 - s) : s;
        const int b = s & 1;

        // Prefetch NEXT step's z before the wait.
        float nzi = 0.f, nzf = 0.f, nzg = 0.f, nzo = 0.f;
        if (s + 1 < TT && tid < 64) {
            const int tn = dir ? (TT - 2 - s) : (s + 1);
            const float* zr = g_zin + (size_t)tn * RTOT + zbase;
            nzi = zr[0]; nzf = zr[256]; nzg = zr[512]; nzo = zr[768];
        }

        if (s > 0) {
            // rearm from warp 7 lane 0 (tid 224): off the writer critical path
            if (b) { mbar_wait_parity(mb1, ph1); ph1 ^= 1; if (tid == 224) MBAR_EXPECT_TX(mb1, 1024); }
            else   { mbar_wait_parity(mb0, ph0); ph0 ^= 1; if (tid == 224) MBAR_EXPECT_TX(mb0, 1024); }
        }

        // matvec partial: 32 packed f32x2 FMAs, 4 independent accumulators.
        const ulonglong2* hp = (const ulonglong2*)&h_s[b][q * 64];
        unsigned long long a0 = 0ull, a1 = 0ull, a2 = 0ull, a3 = 0ull;
#pragma unroll
        for (int k = 0; k < 8; k++) {
            const int m = (k + 2 * q) & 15;
            const ulonglong2 hv = hp[m];
            a0 = ffma2(w2[2 * k],     hv.x, a0);
            a1 = ffma2(w2[2 * k + 1], hv.y, a1);
        }
#pragma unroll
        for (int k = 8; k < 16; k++) {
            const int m = (k + 2 * q) & 15;
            const ulonglong2 hv = hp[m];
            a2 = ffma2(w2[2 * k],     hv.x, a2);
            a3 = ffma2(w2[2 * k + 1], hv.y, a3);
        }
        const float p01 = (lo32(a0) + hi32(a0)) + (lo32(a1) + hi32(a1));
        const float p23 = (lo32(a2) + hi32(a2)) + (lo32(a3) + hi32(a3));
        z_s[lr][q] = p01 + p23;
        __syncthreads();

        if (tid < 64) {
            const float4 pi = *(const float4*)&z_s[jj][0];
            const float4 pf = *(const float4*)&z_s[16 + jj][0];
            const float4 pg = *(const float4*)&z_s[32 + jj][0];
            const float4 po = *(const float4*)&z_s[48 + jj][0];
            const float xi = ((pi.x + pi.y) + (pi.z + pi.w)) + zi;
            const float xf = ((pf.x + pf.y) + (pf.z + pf.w)) + zf;
            const float xg = ((pg.x + pg.y) + (pg.z + pg.w)) + zg;
            const float xo = ((po.x + po.y) + (po.z + po.w)) + zo;
            const float ig = fsigm(xi);
            const float fg = fsigm(xf);
            const float gg = tanh_ap(xg);
            const float og = fsigm(xo);
            c_reg = fg * c_reg + ig * gg;
            const float h = og * tanh_ap(c_reg);

            // sends first (DSMEM messages depart earliest), then global store
            if (s != TT - 1) {
                const int nb = b ^ 1;
#pragma unroll
                for (int u = 0; u < 4; u++)
                    st_async_f32(dst_h[nb][u], h, dst_m[nb][u]);
            }
            if (grp == 0)
                g_hs[(size_t)t * 512 + dir * H2D + (int)rank * 16 + jj] = h;
        }
        zi = nzi; zf = nzf; zg = nzg; zo = nzo;
    }
}

// ---------------------------------------------------------------------------
// Kernel 3: logits = hs @ w_lin^T + b_lin.  One warp per timestep.
// 4 independent accumulators.
// ---------------------------------------------------------------------------
__global__ __launch_bounds__(256) void linear_kernel(
    const float* __restrict__ wlin, const float* __restrict__ blin)
{
    const int warp = threadIdx.x >> 5;
    const int lane = threadIdx.x & 31;
    const int t = blockIdx.x * 8 + warp;

    const float4* hrow = (const float4*)(g_hs + (size_t)t * 512);
    const float4* wrow = (const float4*)(wlin + (size_t)lane * 512);
    float s0 = 0.f, s1 = 0.f, s2 = 0.f, s3 = 0.f;
#pragma unroll 8
    for (int m = 0; m < 128; m += 4) {
        const float4 h0v = hrow[m],     w0v = wrow[m];
        const float4 h1v = hrow[m + 1], w1v = wrow[m + 1];
        const float4 h2v = hrow[m + 2], w2v = wrow[m + 2];
        const float4 h3v = hrow[m + 3], w3v = wrow[m + 3];
        s0 += h0v.x * w0v.x + h0v.y * w0v.y + h0v.z * w0v.z + h0v.w * w0v.w;
        s1 += h1v.x * w1v.x + h1v.y * w1v.y + h1v.z * w1v.z + h1v.w * w1v.w;
        s2 += h2v.x * w2v.x + h2v.y * w2v.y + h2v.z * w2v.z + h2v.w * w2v.w;
        s3 += h3v.x * w3v.x + h3v.y * w3v.y + h3v.z * w3v.z + h3v.w * w3v.w;
    }
    g_logits[(size_t)t * LDIM + lane] = ((s0 + s1) + (s2 + s3)) + blin[lane];
}

// ---------------------------------------------------------------------------
// Kernel 4a: CRF chunk matrices (parallel).
// ---------------------------------------------------------------------------
__global__ __launch_bounds__(1024) void crf_chunk_kernel(const float* __restrict__ trans)
{
    __shared__ float Mbuf[2][32][33];
    __shared__ float rmax[32];

    const int tid = threadIdx.x;
    const int n = tid >> 5;
    const int p = tid & 31;
    const int t0 = blockIdx.x * CLEN;

    float Erow[32];
#pragma unroll
    for (int k = 0; k < 32; k++) Erow[k] = __expf(trans[n * 32 + k]);

    Mbuf[0][n][p] = (n == p) ? 1.f : 0.f;
    __syncthreads();

    float lsc = 0.f;
#pragma unroll 1
    for (int i = 0; i < CLEN; i++) {
        const int rb = i & 1, wb = rb ^ 1;
        const float e = __expf(g_logits[(size_t)(t0 + i) * LDIM + n]);
        float acc = 0.f;
#pragma unroll
        for (int k = 0; k < 32; k++) acc += Erow[k] * Mbuf[rb][k][p];
        acc *= e;

        float m = acc;
#pragma unroll
        for (int o = 16; o; o >>= 1) m = fmaxf(m, __shfl_xor_sync(0xffffffffu, m, o));
        if (p == 0) rmax[n] = m;
        __syncthreads();
        float gm = rmax[0];
#pragma unroll
        for (int k = 1; k < 32; k++) gm = fmaxf(gm, rmax[k]);

        Mbuf[wb][n][p] = acc * __frcp_rn(gm);
        lsc += __logf(gm);
        __syncthreads();
    }

    g_P[(size_t)blockIdx.x * 1024 + n * 32 + p] = Mbuf[CLEN & 1][n][p];
    if (tid == 0) g_lsc[blockIdx.x] = lsc;
}

// ---------------------------------------------------------------------------
// Kernel 4b: CRF final combine + gold path.
// ---------------------------------------------------------------------------
__global__ void crf_final_kernel(const float* __restrict__ trans,
                                 const int* __restrict__ target,
                                 float* __restrict__ out)
{
    __shared__ float tr_s[32 * 33];
    __shared__ float beta[32];
    __shared__ float gold_s;

    const int tid  = threadIdx.x;   // blockDim = 64
    const int warp = tid >> 5;
    const int lane = tid & 31;

    for (int i = tid; i < 1024; i += 64) {
        const int n = i >> 5, p = i & 31;
        tr_s[n * 33 + p] = trans[i];
    }
    __syncthreads();

    if (warp == 1) {
        float gs = 0.f;
        for (int t = lane; t < TT; t += 32) {
            const int nxt  = target[t];
            const int prev = (t == 0) ? 0 : target[t - 1];
            gs += tr_s[nxt * 33 + prev] + g_logits[(size_t)t * LDIM + nxt];
        }
#pragma unroll
        for (int o = 16; o; o >>= 1) gs += __shfl_xor_sync(0xffffffffu, gs, o);
        gs += tr_s[31 * 33 + target[TT - 1]];
        if (lane == 0) gold_s = gs;
    } else {
        float lsc = 0.f;
#pragma unroll
        for (int i = 0; i < 4; i++) lsc += g_lsc[lane + 32 * i];
#pragma unroll
        for (int o = 16; o; o >>= 1) lsc += __shfl_xor_sync(0xffffffffu, lsc, o);

        beta[lane] = (lane == 0) ? 1.f : 0.f;
        __syncwarp();

        float4 pr[8];
#pragma unroll
        for (int j = 0; j < 8; j++)
            pr[j] = ((const float4*)(g_P + (size_t)lane * 32))[j];

        for (int c = 0; c < NCHUNK; c++) {
            float4 cur[8];
#pragma unroll
            for (int j = 0; j < 8; j++) cur[j] = pr[j];
            if (c < NCHUNK - 1) {
#pragma unroll
                for (int j = 0; j < 8; j++)
                    pr[j] = ((const float4*)(g_P + (size_t)(c + 1) * 1024 + lane * 32))[j];
            }
            float acc = 0.f;
#pragma unroll
            for (int j = 0; j < 8; j++) {
                acc += cur[j].x * beta[4 * j + 0];
                acc += cur[j].y * beta[4 * j + 1];
                acc += cur[j].z * beta[4 * j + 2];
                acc += cur[j].w * beta[4 * j + 3];
            }
            float m = acc;
#pragma unroll
            for (int o = 16; o; o >>= 1) m = fmaxf(m, __shfl_xor_sync(0xffffffffu, m, o));
            lsc += __logf(m);
            __syncwarp();
            beta[lane] = acc * __frcp_rn(m);
            __syncwarp();
        }

        float v = beta[lane] * __expf(tr_s[31 * 33 + lane]);
#pragma unroll
        for (int o = 16; o; o >>= 1) v += __shfl_xor_sync(0xffffffffu, v, o);
        const float fwd = __logf(v) + lsc;
        if (lane == 0) beta[0] = fwd;
    }

    __syncthreads();
    if (tid == 0) out[0] = beta[0] - gold_s;
}

// ---------------------------------------------------------------------------
// Launch
// ---------------------------------------------------------------------------
extern "C" void kernel_launch(void* const* d_in, const int* in_sizes, int n_in,
                              void* d_out, int out_size)
{
    const int*   ids    = (const int*)  d_in[0];
    const int*   target = (const int*)  d_in[2];
    const float* emb    = (const float*)d_in[3];
    const float* wihf   = (const float*)d_in[4];
    const float* whhf   = (const float*)d_in[5];
    const float* bf     = (const float*)d_in[6];
    const float* wihb   = (const float*)d_in[7];
    const float* whhb   = (const float*)d_in[8];
    const float* bb     = (const float*)d_in[9];
    const float* wlin   = (const float*)d_in[10];
    const float* blin   = (const float*)d_in[11];
    const float* trans  = (const float*)d_in[12];
    const float* h0     = (const float*)d_in[13];
    const float* c0     = (const float*)d_in[14];

    cudaFuncSetAttribute(lstm_kernel, cudaFuncAttributeNonPortableClusterSizeAllowed, 1);

    dim3 g1(RTOT / 64, TT / 64);
    zin_kernel<<<g1, 256>>>(ids, emb, wihf, wihb, bf, bb);
    lstm_kernel<<<32, 256>>>(whhf, whhb, h0, c0);
    linear_kernel<<<TT / 8, 256>>>(wlin, blin);
    crf_chunk_kernel<<<NCHUNK, 1024>>>(trans);
    crf_final_kernel<<<1, 64>>>(trans, target, (float*)d_out);
}

// round 13
// speedup vs baseline: 1.8922x; 1.2289x over previous
#include <cuda_runtime.h>
#include <cuda_bf16.h>
#include <cstdint>
#include <math.h>

// ---------------------------------------------------------------------------
// Problem constants
// ---------------------------------------------------------------------------
#define TT   2048
#define EDIM 256
#define H2D  256
#define LDIM 32
#define RTOT 2048   // 2 dirs * 4 gates * 256
#define NCHUNK 128
#define CLEN   16   // CRF steps per chunk

// ---------------------------------------------------------------------------
// Scratch
// ---------------------------------------------------------------------------
__device__ float g_zin[TT * RTOT];        // 16 MB (L2-resident)
__device__ float g_hs[TT * 512];          // 4 MB
__device__ float g_logits[TT * LDIM];     // 256 KB
__device__ float g_P[NCHUNK * 1024];      // 512 KB
__device__ float g_lsc[NCHUNK];

// ---------------------------------------------------------------------------
// Helpers
// ---------------------------------------------------------------------------
__device__ __forceinline__ uint32_t s2u(const void* p) {
    uint32_t a;
    asm("{ .reg .u64 t; cvta.to.shared.u64 t, %1; cvt.u32.u64 %0, t; }"
        : "=r"(a) : "l"(p));
    return a;
}
__device__ __forceinline__ void cluster_sync_() {
    asm volatile("barrier.cluster.arrive.aligned;\n\t"
                 "barrier.cluster.wait.aligned;" ::: "memory");
}
__device__ __forceinline__ uint32_t my_ctarank() {
    uint32_t r;
    asm("mov.u32 %0, %%cluster_ctarank;" : "=r"(r));
    return r;
}
__device__ __forceinline__ uint32_t mapa_(uint32_t a, uint32_t r) {
    uint32_t d;
    asm("mapa.shared::cluster.u32 %0, %1, %2;" : "=r"(d) : "r"(a), "r"(r));
    return d;
}
__device__ __forceinline__ unsigned long long ffma2(unsigned long long a,
                                                    unsigned long long b,
                                                    unsigned long long c) {
    unsigned long long d;
    asm("fma.rn.f32x2 %0, %1, %2, %3;" : "=l"(d) : "l"(a), "l"(b), "l"(c));
    return d;
}
__device__ __forceinline__ float lo32(unsigned long long v) { return __uint_as_float((unsigned)v); }
__device__ __forceinline__ float hi32(unsigned long long v) { return __uint_as_float((unsigned)(v >> 32)); }

__device__ __forceinline__ void st_async_f32(uint32_t daddr, float v, uint32_t dmbar) {
    asm volatile("st.async.shared::cluster.mbarrier::complete_tx::bytes.f32 [%0], %1, [%2];"
                 :: "r"(daddr), "f"(v), "r"(dmbar) : "memory");
}

#define MBAR_INIT(a, n) \
    asm volatile("mbarrier.init.shared.b64 [%0], %1;" :: "r"(a), "r"((uint32_t)(n)) : "memory")
#define MBAR_EXPECT_TX(a, n) \
    asm volatile("mbarrier.arrive.expect_tx.shared.b64 _, [%0], %1;" :: "r"(a), "r"((uint32_t)(n)) : "memory")

__device__ __forceinline__ void mbar_wait_parity(uint32_t mbar, uint32_t parity) {
    uint32_t done;
    asm volatile(
        "{\n\t.reg .pred p;\n\t"
        "mbarrier.try_wait.parity.acquire.cta.shared::cta.b64 p, [%1], %2;\n\t"
        "selp.b32 %0, 1, 0, p;\n\t}"
        : "=r"(done) : "r"(mbar), "r"(parity) : "memory");
    if (!done) {
        asm volatile(
            "{\n\t.reg .pred P1;\n\t"
            "WL_%=:\n\t"
            "mbarrier.try_wait.parity.acquire.cta.shared::cta.b64 P1, [%0], %1, 0x989680;\n\t"
            "@P1 bra.uni WD_%=;\n\t"
            "bra.uni WL_%=;\n\t"
            "WD_%=:\n\t}"
            :: "r"(mbar), "r"(parity) : "memory");
    }
}

// Fast activations (rel_err 0.0 proven over 2048 steps)
__device__ __forceinline__ float tanh_ap(float x) {
    float y;
    asm("tanh.approx.f32 %0, %1;" : "=f"(y) : "f"(x));
    return y;
}
__device__ __forceinline__ float fsigm(float x) {
    return __fmaf_rn(0.5f, tanh_ap(0.5f * x), 0.5f);
}

// ---------------------------------------------------------------------------
// Kernel 1: Zin[t][col] = emb[ids[t]] @ Wih^T + b
// ---------------------------------------------------------------------------
__global__ __launch_bounds__(256) void zin_kernel(
    const int* __restrict__ ids, const float* __restrict__ emb,
    const float* __restrict__ wihf, const float* __restrict__ wihb,
    const float* __restrict__ bf, const float* __restrict__ bb)
{
    __shared__ float As[32][68];
    __shared__ float Bs[32][68];
    __shared__ int gids[64];

    const int tid = threadIdx.x;
    const int tx = tid & 15;
    const int ty = tid >> 4;
    const int tRow = blockIdx.y * 64;
    const int nCol = blockIdx.x * 64;

    if (tid < 64) gids[tid] = ids[tRow + tid];
    __syncthreads();

    float acc[4][4];
#pragma unroll
    for (int i = 0; i < 4; i++)
#pragma unroll
        for (int j = 0; j < 4; j++) acc[i][j] = 0.f;

    for (int kk = 0; kk < EDIM; kk += 32) {
#pragma unroll
        for (int u = 0; u < 2; u++) {
            int idx = tid + u * 256;
            int row = idx >> 3;
            int c4  = (idx & 7) * 4;
            const float4 av = *(const float4*)(emb + (size_t)gids[row] * EDIM + kk + c4);
            As[c4 + 0][row] = av.x; As[c4 + 1][row] = av.y;
            As[c4 + 2][row] = av.z; As[c4 + 3][row] = av.w;
            int brow = nCol + row;
            const float* bp = (brow < 1024)
                ? (wihf + (size_t)brow * EDIM)
                : (wihb + (size_t)(brow - 1024) * EDIM);
            const float4 bv = *(const float4*)(bp + kk + c4);
            Bs[c4 + 0][row] = bv.x; Bs[c4 + 1][row] = bv.y;
            Bs[c4 + 2][row] = bv.z; Bs[c4 + 3][row] = bv.w;
        }
        __syncthreads();
#pragma unroll
        for (int k = 0; k < 32; k++) {
            const float4 av = *(const float4*)&As[k][ty * 4];
            const float4 bv = *(const float4*)&Bs[k][tx * 4];
            const float ar[4] = {av.x, av.y, av.z, av.w};
            const float br[4] = {bv.x, bv.y, bv.z, bv.w};
#pragma unroll
            for (int i = 0; i < 4; i++)
#pragma unroll
                for (int j = 0; j < 4; j++) acc[i][j] += ar[i] * br[j];
        }
        __syncthreads();
    }

    const int colBase = nCol + tx * 4;
    float bias[4];
#pragma unroll
    for (int j = 0; j < 4; j++) {
        int c = colBase + j;
        bias[j] = (c < 1024) ? bf[c] : bb[c - 1024];
    }
#pragma unroll
    for (int i = 0; i < 4; i++) {
        int row = tRow + ty * 4 + i;
        float4 o;
        o.x = acc[i][0] + bias[0];
        o.y = acc[i][1] + bias[1];
        o.z = acc[i][2] + bias[2];
        o.w = acc[i][3] + bias[3];
        *(float4*)(g_zin + (size_t)row * RTOT + colBase) = o;
    }
}

// ---------------------------------------------------------------------------
// Kernel 2: BiLSTM recurrence. 2 clusters of 16 CTAs (fwd / bwd).
// SPLIT-MBAR variant: 4 mbarriers per buffer, indexed by source-CTA group
// (g = src_rank>>2). Sources 4g..4g+3 land in h_s columns [64g, 64g+64) =
// column quarter q=g. Warp w handles quarter q = w&3 and waits ONLY its own
// mbar, so waits+arrival processing spread across 4 barriers. Messaging is
// unchanged (256 scalar st.async / CTA / step, same fan-out).
// ---------------------------------------------------------------------------
__global__ void __launch_bounds__(256, 1) __cluster_dims__(16, 1, 1)
lstm_kernel(const float* __restrict__ whhf, const float* __restrict__ whhb,
            const float* __restrict__ h0, const float* __restrict__ c0)
{
    __shared__ __align__(128) float h_s[2][256];
    __shared__ __align__(16) float z_s[64][4];   // [gate row][rotated quarter slot]
    __shared__ unsigned long long mbar[2][4];

    const int tid  = threadIdx.x;
    const int w    = tid >> 5;
    const int lane = tid & 31;
    const int dir  = blockIdx.x >> 4;
    const uint32_t rank = my_ctarank();

    const int q    = w & 3;            // column quarter, per-warp
    const int half = w >> 2;           // 0 or 1
    const int lr   = half * 32 + lane; // local gate row 0..63
    const int gate = lr >> 4;
    const int jr   = lr & 15;
    const int grow = gate * 256 + (int)rank * 16 + jr;

    const float* whh = dir ? whhb : whhf;

    unsigned long long w2[32];
    {
        const float* wr = whh + (size_t)grow * H2D + q * 64;
#pragma unroll
        for (int k = 0; k < 16; k++) {
            int m = (k + 2 * q) & 15;
            const unsigned long long* p = (const unsigned long long*)(wr + m * 4);
            w2[2 * k]     = p[0];
            w2[2 * k + 1] = p[1];
        }
    }

    const int jj  = tid & 15;        // writer's h index (tid < 64)
    const int grp = tid >> 4;        // writer's fan-out group (0..3 for tid<64)

    float c_reg = 0.f;
    if (tid < 64) c_reg = c0[dir * H2D + (int)rank * 16 + jj];

    h_s[0][tid] = h0[dir * H2D + tid];

    // Fan-out: writer (jj, grp) sends its h to ranks grp*4..grp*4+3.
    // Dest mbar index = OUR source group (rank>>2).
    const uint32_t mygrp = rank >> 2;
    uint32_t dst_h[2][4], dst_m[2][4];
    if (tid < 64) {
        const uint32_t off = 4u * ((uint32_t)rank * 16 + (uint32_t)jj);
        const uint32_t h0a = s2u(&h_s[0][0]);
        const uint32_t h1a = s2u(&h_s[1][0]);
        const uint32_t m0a = s2u(&mbar[0][mygrp]);
        const uint32_t m1a = s2u(&mbar[1][mygrp]);
#pragma unroll
        for (int u = 0; u < 4; u++) {
            const uint32_t r = (uint32_t)(grp * 4 + u);
            dst_h[0][u] = mapa_(h0a, r) + off;
            dst_h[1][u] = mapa_(h1a, r) + off;
            dst_m[0][u] = mapa_(m0a, r);
            dst_m[1][u] = mapa_(m1a, r);
        }
    }

    // Local mbar addresses (this warp waits mbar[b][q])
    const uint32_t mbq[2] = { s2u(&mbar[0][q]), s2u(&mbar[1][q]) };
    if (tid == 0) {
#pragma unroll
        for (int g = 0; g < 4; g++) {
            MBAR_INIT(s2u(&mbar[0][g]), 1);
            MBAR_INIT(s2u(&mbar[1][g]), 1);
            MBAR_EXPECT_TX(s2u(&mbar[0][g]), 256);
            MBAR_EXPECT_TX(s2u(&mbar[1][g]), 256);
        }
    }
    __syncthreads();
    cluster_sync_();

    const int zbase = dir * 1024 + (int)rank * 16 + jj;
    uint32_t ph[2] = { 0, 0 };

    // Software pipeline: z for step 0 loaded before the loop (writers only).
    float zi = 0.f, zf = 0.f, zg = 0.f, zo = 0.f;
    if (tid < 64) {
        const int t0 = dir ? (TT - 1) : 0;
        const float* zr = g_zin + (size_t)t0 * RTOT + zbase;
        zi = zr[0]; zf = zr[256]; zg = zr[512]; zo = zr[768];
    }

    // rotated z_s slot: order-free (writer sums all 4), kills bank conflicts
    const int zslot = (q + (lr >> 3)) & 3;

    for (int s = 0; s < TT; s++) {
        const int t = dir ? (TT - 1 - s) : s;
        const int b = s & 1;

        // Prefetch NEXT step's z before the wait (writers only).
        float nzi = 0.f, nzf = 0.f, nzg = 0.f, nzo = 0.f;
        if (s + 1 < TT && tid < 64) {
            const int tn = dir ? (TT - 2 - s) : (s + 1);
            const float* zr = g_zin + (size_t)tn * RTOT + zbase;
            nzi = zr[0]; nzf = zr[256]; nzg = zr[512]; nzo = zr[768];
        }

        if (s > 0) {
            // warp w waits only its quarter's mbar; rearm once per mbar by
            // lane 0 of warps 4..7 (off the writer warps 0-1).
            mbar_wait_parity(mbq[b], ph[b]); ph[b] ^= 1;
            if (half && lane == 0) MBAR_EXPECT_TX(mbq[b], 256);
        }

        // matvec partial over quarter q (64 cols): 32 packed f32x2 FMAs.
        const ulonglong2* hp = (const ulonglong2*)&h_s[b][q * 64];
        unsigned long long a0 = 0ull, a1 = 0ull;
#pragma unroll
        for (int k = 0; k < 16; k++) {
            const int m = (k + 2 * q) & 15;
            const ulonglong2 hv = hp[m];
            a0 = ffma2(w2[2 * k],     hv.x, a0);
            a1 = ffma2(w2[2 * k + 1], hv.y, a1);
        }
        z_s[lr][zslot] = (lo32(a0) + hi32(a0)) + (lo32(a1) + hi32(a1));
        __syncthreads();

        if (tid < 64) {
            const float4 pi = *(const float4*)&z_s[jj][0];
            const float4 pf = *(const float4*)&z_s[16 + jj][0];
            const float4 pg = *(const float4*)&z_s[32 + jj][0];
            const float4 po = *(const float4*)&z_s[48 + jj][0];
            const float xi = ((pi.x + pi.y) + (pi.z + pi.w)) + zi;
            const float xf = ((pf.x + pf.y) + (pf.z + pf.w)) + zf;
            const float xg = ((pg.x + pg.y) + (pg.z + pg.w)) + zg;
            const float xo = ((po.x + po.y) + (po.z + po.w)) + zo;
            const float ig = fsigm(xi);
            const float fg = fsigm(xf);
            const float gg = tanh_ap(xg);
            const float og = fsigm(xo);
            c_reg = fg * c_reg + ig * gg;
            const float h = og * tanh_ap(c_reg);

            if (s != TT - 1) {
                const int nb = b ^ 1;
#pragma unroll
                for (int u = 0; u < 4; u++)
                    st_async_f32(dst_h[nb][u], h, dst_m[nb][u]);
            }
            if (grp == 0)
                g_hs[(size_t)t * 512 + dir * H2D + (int)rank * 16 + jj] = h;
        }
        zi = nzi; zf = nzf; zg = nzg; zo = nzo;
    }
}

// ---------------------------------------------------------------------------
// Kernel 3: logits = hs @ w_lin^T + b_lin.  One warp per timestep.
// ---------------------------------------------------------------------------
__global__ __launch_bounds__(256) void linear_kernel(
    const float* __restrict__ wlin, const float* __restrict__ blin)
{
    const int warp = threadIdx.x >> 5;
    const int lane = threadIdx.x & 31;
    const int t = blockIdx.x * 8 + warp;

    const float4* hrow = (const float4*)(g_hs + (size_t)t * 512);
    const float4* wrow = (const float4*)(wlin + (size_t)lane * 512);
    float s0 = 0.f, s1 = 0.f, s2 = 0.f, s3 = 0.f;
#pragma unroll 8
    for (int m = 0; m < 128; m += 4) {
        const float4 h0v = hrow[m],     w0v = wrow[m];
        const float4 h1v = hrow[m + 1], w1v = wrow[m + 1];
        const float4 h2v = hrow[m + 2], w2v = wrow[m + 2];
        const float4 h3v = hrow[m + 3], w3v = wrow[m + 3];
        s0 += h0v.x * w0v.x + h0v.y * w0v.y + h0v.z * w0v.z + h0v.w * w0v.w;
        s1 += h1v.x * w1v.x + h1v.y * w1v.y + h1v.z * w1v.z + h1v.w * w1v.w;
        s2 += h2v.x * w2v.x + h2v.y * w2v.y + h2v.z * w2v.z + h2v.w * w2v.w;
        s3 += h3v.x * w3v.x + h3v.y * w3v.y + h3v.z * w3v.z + h3v.w * w3v.w;
    }
    g_logits[(size_t)t * LDIM + lane] = ((s0 + s1) + (s2 + s3)) + blin[lane];
}

// ---------------------------------------------------------------------------
// Kernel 4a: CRF chunk matrices (parallel).
// ---------------------------------------------------------------------------
__global__ __launch_bounds__(1024) void crf_chunk_kernel(const float* __restrict__ trans)
{
    __shared__ float Mbuf[2][32][33];
    __shared__ float rmax[32];

    const int tid = threadIdx.x;
    const int n = tid >> 5;
    const int p = tid & 31;
    const int t0 = blockIdx.x * CLEN;

    float Erow[32];
#pragma unroll
    for (int k = 0; k < 32; k++) Erow[k] = __expf(trans[n * 32 + k]);

    Mbuf[0][n][p] = (n == p) ? 1.f : 0.f;
    __syncthreads();

    float lsc = 0.f;
#pragma unroll 1
    for (int i = 0; i < CLEN; i++) {
        const int rb = i & 1, wb = rb ^ 1;
        const float e = __expf(g_logits[(size_t)(t0 + i) * LDIM + n]);
        float acc = 0.f;
#pragma unroll
        for (int k = 0; k < 32; k++) acc += Erow[k] * Mbuf[rb][k][p];
        acc *= e;

        float m = acc;
#pragma unroll
        for (int o = 16; o; o >>= 1) m = fmaxf(m, __shfl_xor_sync(0xffffffffu, m, o));
        if (p == 0) rmax[n] = m;
        __syncthreads();
        float gm = rmax[0];
#pragma unroll
        for (int k = 1; k < 32; k++) gm = fmaxf(gm, rmax[k]);

        Mbuf[wb][n][p] = acc * __frcp_rn(gm);
        lsc += __logf(gm);
        __syncthreads();
    }

    g_P[(size_t)blockIdx.x * 1024 + n * 32 + p] = Mbuf[CLEN & 1][n][p];
    if (tid == 0) g_lsc[blockIdx.x] = lsc;
}

// ---------------------------------------------------------------------------
// Kernel 4b: CRF final combine + gold path.
// ---------------------------------------------------------------------------
__global__ void crf_final_kernel(const float* __restrict__ trans,
                                 const int* __restrict__ target,
                                 float* __restrict__ out)
{
    __shared__ float tr_s[32 * 33];
    __shared__ float beta[32];
    __shared__ float gold_s;

    const int tid  = threadIdx.x;   // blockDim = 64
    const int warp = tid >> 5;
    const int lane = tid & 31;

    for (int i = tid; i < 1024; i += 64) {
        const int n = i >> 5, p = i & 31;
        tr_s[n * 33 + p] = trans[i];
    }
    __syncthreads();

    if (warp == 1) {
        float gs = 0.f;
        for (int t = lane; t < TT; t += 32) {
            const int nxt  = target[t];
            const int prev = (t == 0) ? 0 : target[t - 1];
            gs += tr_s[nxt * 33 + prev] + g_logits[(size_t)t * LDIM + nxt];
        }
#pragma unroll
        for (int o = 16; o; o >>= 1) gs += __shfl_xor_sync(0xffffffffu, gs, o);
        gs += tr_s[31 * 33 + target[TT - 1]];
        if (lane == 0) gold_s = gs;
    } else {
        float lsc = 0.f;
#pragma unroll
        for (int i = 0; i < 4; i++) lsc += g_lsc[lane + 32 * i];
#pragma unroll
        for (int o = 16; o; o >>= 1) lsc += __shfl_xor_sync(0xffffffffu, lsc, o);

        beta[lane] = (lane == 0) ? 1.f : 0.f;
        __syncwarp();

        float4 pr[8];
#pragma unroll
        for (int j = 0; j < 8; j++)
            pr[j] = ((const float4*)(g_P + (size_t)lane * 32))[j];

        for (int c = 0; c < NCHUNK; c++) {
            float4 cur[8];
#pragma unroll
            for (int j = 0; j < 8; j++) cur[j] = pr[j];
            if (c < NCHUNK - 1) {
#pragma unroll
                for (int j = 0; j < 8; j++)
                    pr[j] = ((const float4*)(g_P + (size_t)(c + 1) * 1024 + lane * 32))[j];
            }
            float acc = 0.f;
#pragma unroll
            for (int j = 0; j < 8; j++) {
                acc += cur[j].x * beta[4 * j + 0];
                acc += cur[j].y * beta[4 * j + 1];
                acc += cur[j].z * beta[4 * j + 2];
                acc += cur[j].w * beta[4 * j + 3];
            }
            float m = acc;
#pragma unroll
            for (int o = 16; o; o >>= 1) m = fmaxf(m, __shfl_xor_sync(0xffffffffu, m, o));
            lsc += __logf(m);
            __syncwarp();
            beta[lane] = acc * __frcp_rn(m);
            __syncwarp();
        }

        float v = beta[lane] * __expf(tr_s[31 * 33 + lane]);
#pragma unroll
        for (int o = 16; o; o >>= 1) v += __shfl_xor_sync(0xffffffffu, v, o);
        const float fwd = __logf(v) + lsc;
        if (lane == 0) beta[0] = fwd;
    }

    __syncthreads();
    if (tid == 0) out[0] = beta[0] - gold_s;
}

// ---------------------------------------------------------------------------
// Launch
// ---------------------------------------------------------------------------
extern "C" void kernel_launch(void* const* d_in, const int* in_sizes, int n_in,
                              void* d_out, int out_size)
{
    const int*   ids    = (const int*)  d_in[0];
    const int*   target = (const int*)  d_in[2];
    const float* emb    = (const float*)d_in[3];
    const float* wihf   = (const float*)d_in[4];
    const float* whhf   = (const float*)d_in[5];
    const float* bf     = (const float*)d_in[6];
    const float* wihb   = (const float*)d_in[7];
    const float* whhb   = (const float*)d_in[8];
    const float* bb     = (const float*)d_in[9];
    const float* wlin   = (const float*)d_in[10];
    const float* blin   = (const float*)d_in[11];
    const float* trans  = (const float*)d_in[12];
    const float* h0     = (const float*)d_in[13];
    const float* c0     = (const float*)d_in[14];

    cudaFuncSetAttribute(lstm_kernel, cudaFuncAttributeNonPortableClusterSizeAllowed, 1);

    dim3 g1(RTOT / 64, TT / 64);
    zin_kernel<<<g1, 256>>>(ids, emb, wihf, wihb, bf, bb);
    lstm_kernel<<<32, 256>>>(whhf, whhb, h0, c0);
    linear_kernel<<<TT / 8, 256>>>(wlin, blin);
    crf_chunk_kernel<<<NCHUNK, 1024>>>(trans);
    crf_final_kernel<<<1, 64>>>(trans, target, (float*)d_out);
}